// round 8
// baseline (speedup 1.0000x reference)
#include <cuda_runtime.h>
#include <cuda_fp16.h>
#include <cstdint>

#define NEDGES 2000000
#define TILE_M 128
#define NTILES (NEDGES / TILE_M)
#define TPB 256

// activation buffers: [128 rows][136 fp16] (272 B stride, conflict-free ldmatrix)
#define ROWB 272
#define SM_XH 0
#define SM_YH 34816
#define SM_P  69632             // float[2][128][2]
#define SM_B4 71680             // float[2]
#define SMEM_BYTES 71744

#define LO_SCALE 2048.0f        // 2^11: keep B-lo in fp16 normal range
#define LO_INV   (1.0f / 2048.0f)

__device__ __forceinline__ uint32_t smem_u32(const void* p) {
    uint32_t a;
    asm("{ .reg .u64 t; cvta.to.shared.u64 t, %1; cvt.u32.u64 %0, t; }" : "=r"(a) : "l"(p));
    return a;
}
__device__ __forceinline__ float lrelu(float z) { return fmaxf(z, 0.01f * z); }

// pack 2 f32 -> fp16x2 (a in low half)
__device__ __forceinline__ uint32_t pkh2(float a, float b) {
    __half2 h = __floats2half2_rn(a, b);
    return *(uint32_t*)&h;
}

__device__ __forceinline__ void ldsm4(uint32_t addr, uint32_t& a0, uint32_t& a1,
                                      uint32_t& a2, uint32_t& a3) {
    asm volatile("ldmatrix.sync.aligned.m8n8.x4.shared.b16 {%0,%1,%2,%3}, [%4];"
                 : "=r"(a0), "=r"(a1), "=r"(a2), "=r"(a3) : "r"(addr));
}
__device__ __forceinline__ void mma16816(float* d, uint32_t a0, uint32_t a1,
                                         uint32_t a2, uint32_t a3,
                                         uint32_t b0, uint32_t b1) {
    asm volatile(
        "mma.sync.aligned.m16n8k16.row.col.f32.f16.f16.f32 "
        "{%0,%1,%2,%3}, {%4,%5,%6,%7}, {%8,%9}, {%0,%1,%2,%3};"
        : "+f"(d[0]), "+f"(d[1]), "+f"(d[2]), "+f"(d[3])
        : "r"(a0), "r"(a1), "r"(a2), "r"(a3), "r"(b0), "r"(b1));
}

// 8x8 B fragment (col-major k8 x n8) via element fetch f(k,n): fp16 hi + scaled lo
template <typename F>
__device__ __forceinline__ void make_hfrag_f(F f, int k0, int n0, int lane,
                                             uint32_t& h, uint32_t& l) {
    int g = lane >> 2, tg = lane & 3;
    int k = k0 + tg * 2, n = n0 + g;
    float wa = f(k, n), wb = f(k + 1, n);
    h = pkh2(wa, wb);
    __half2 hh = *(__half2*)&h;
    float ra = (wa - __low2float(hh)) * LO_SCALE;
    float rb = (wb - __high2float(hh)) * LO_SCALE;
    l = pkh2(ra, rb);
}

__global__ void __launch_bounds__(TPB, 1)
regressor_mma_kernel(const float* __restrict__ x_src,
                     const float* __restrict__ x_dst,
                     const int* __restrict__ eidx,
                     const float* __restrict__ ew1, const float* __restrict__ eb1,
                     const float* __restrict__ ww1, const float* __restrict__ wb1,
                     const float* __restrict__ ew2, const float* __restrict__ eb2,
                     const float* __restrict__ ww2, const float* __restrict__ wb2,
                     const float* __restrict__ ew3, const float* __restrict__ eb3,
                     const float* __restrict__ ww3, const float* __restrict__ wb3,
                     const float* __restrict__ ew4, const float* __restrict__ eb4,
                     const float* __restrict__ ww4, const float* __restrict__ wb4,
                     float* __restrict__ out) {
    extern __shared__ char smem[];
    const uint32_t smb = smem_u32(smem);
    const int tid = threadIdx.x;
    const int wid = tid >> 5, lane = tid & 31;

    // warp roles
    const int nw1 = wid * 16;              // L1: 16-col slice of fused 128
    const int branch = wid >> 2;           // L2/L3/L4: 0 = exists, 1 = weight
    const int w4 = wid & 3;
    const int nw2 = w4 * 16;               // L2: 16-col slice of branch's 64
    const int mg = w4 >> 1;                // L3: m-group (0: mt 0-3, 1: mt 4-7)
    const int nw3 = (w4 & 1) * 16;         // L3: 16-col slice of branch's 32

    // ---------- per-warp weight fragments (registers, built once) ----------
    const float* W2 = branch ? ww2 : ew2;  // [64][64]
    const float* W3 = branch ? ww3 : ew3;  // [64][32]
    const float* B2 = branch ? wb2 : eb2;
    const float* B3 = branch ? wb3 : eb3;
    const float* W4 = branch ? ww4 : ew4;

    auto w1f = [&](int k, int n) {         // fused L1 weight [128][128]
        return (n < 64) ? ew1[k * 64 + n] : ww1[k * 64 + (n - 64)];
    };
    auto w2f = [&](int k, int n) { return W2[k * 64 + n]; };
    auto w3f = [&](int k, int n) { return W3[k * 32 + n]; };

    uint32_t B1h[8][2][2], B1l[8][2][2];
#pragma unroll
    for (int kt = 0; kt < 8; kt++)
#pragma unroll
        for (int nt = 0; nt < 2; nt++)
#pragma unroll
            for (int r = 0; r < 2; r++)
                make_hfrag_f(w1f, kt * 16 + r * 8, nw1 + nt * 8, lane,
                             B1h[kt][nt][r], B1l[kt][nt][r]);

    uint32_t B2h[4][2][2], B2l[4][2][2];
#pragma unroll
    for (int kt = 0; kt < 4; kt++)
#pragma unroll
        for (int nt = 0; nt < 2; nt++)
#pragma unroll
            for (int r = 0; r < 2; r++)
                make_hfrag_f(w2f, kt * 16 + r * 8, nw2 + nt * 8, lane,
                             B2h[kt][nt][r], B2l[kt][nt][r]);

    uint32_t B3h[4][2][2], B3l[4][2][2];
#pragma unroll
    for (int kt = 0; kt < 4; kt++)
#pragma unroll
        for (int nt = 0; nt < 2; nt++)
#pragma unroll
            for (int r = 0; r < 2; r++)
                make_hfrag_f(w3f, kt * 16 + r * 8, nw3 + nt * 8, lane,
                             B3h[kt][nt][r], B3l[kt][nt][r]);

    // per-thread biases / final weights for covered columns
    float b1v[2][2], b2v[2][2], b3v[2][2], w4v[2][2];
#pragma unroll
    for (int nt = 0; nt < 2; nt++)
#pragma unroll
        for (int j = 0; j < 2; j++) {
            int c1 = nw1 + nt * 8 + (lane & 3) * 2 + j;
            b1v[nt][j] = (c1 < 64) ? eb1[c1] : wb1[c1 - 64];
            int c2 = nw2 + nt * 8 + (lane & 3) * 2 + j;
            b2v[nt][j] = B2[c2];
            int c3 = nw3 + nt * 8 + (lane & 3) * 2 + j;
            b3v[nt][j] = B3[c3];
            w4v[nt][j] = W4[c3];
        }
    if (tid == 0) {
        *(float*)(smem + SM_B4 + 0) = eb4[0];
        *(float*)(smem + SM_B4 + 4) = wb4[0];
    }
    __syncthreads();

    const uint32_t xh = smb + SM_XH;
    const uint32_t yh = smb + SM_YH;

    for (int t = blockIdx.x; t < NTILES; t += gridDim.x) {
        // ===== gather: warp w owns edges [16w,16w+16); lanes 0-15 src, 16-31 dst =====
        {
            const int half = lane >> 4;
            const int c16 = lane & 15;
#pragma unroll 2
            for (int i = 0; i < 16; i++) {
                int m = wid * 16 + i;
                int e = t * TILE_M + m;
                int idx = half ? eidx[NEDGES + e] : eidx[e];
                const float* row = (half ? x_dst : x_src) + (size_t)idx * 64;
                float4 v = ((const float4*)row)[c16];
                uint32_t h0 = pkh2(v.x, v.y);
                uint32_t h1 = pkh2(v.z, v.w);
                uint32_t off = (uint32_t)m * ROWB + half * 128u + c16 * 8u;
                *(uint2*)(smem + SM_XH + off) = make_uint2(h0, h1);
            }
        }
        __syncthreads();

        // ===== L1: X[128x128] -> Y[128x128], 16-col slice per warp =====
        {
#pragma unroll 1
            for (int mt = 0; mt < 8; mt++) {
                int m0 = mt * 16;
                float aP[2][4] = {}, aQ[2][4] = {};
                uint32_t arow = (uint32_t)(m0 + (lane & 15)) * ROWB + (lane >> 4) * 16u;
#pragma unroll
                for (int kt = 0; kt < 8; kt++) {
                    uint32_t h0, h1, h2, h3;
                    ldsm4(xh + arow + kt * 32u, h0, h1, h2, h3);
#pragma unroll
                    for (int nt = 0; nt < 2; nt++) {
                        mma16816(aP[nt], h0, h1, h2, h3, B1h[kt][nt][0], B1h[kt][nt][1]);
                        mma16816(aQ[nt], h0, h1, h2, h3, B1l[kt][nt][0], B1l[kt][nt][1]);
                    }
                }
#pragma unroll
                for (int nt = 0; nt < 2; nt++) {
                    float v0 = lrelu(fmaf(aQ[nt][0], LO_INV, aP[nt][0]) + b1v[nt][0]);
                    float v1 = lrelu(fmaf(aQ[nt][1], LO_INV, aP[nt][1]) + b1v[nt][1]);
                    float v2 = lrelu(fmaf(aQ[nt][2], LO_INV, aP[nt][2]) + b1v[nt][0]);
                    float v3 = lrelu(fmaf(aQ[nt][3], LO_INV, aP[nt][3]) + b1v[nt][1]);
                    uint32_t col2 = (uint32_t)(nw1 + nt * 8 + (lane & 3) * 2) * 2u;
                    uint32_t o0 = (uint32_t)(m0 + (lane >> 2)) * ROWB + col2;
                    uint32_t o1 = (uint32_t)(m0 + 8 + (lane >> 2)) * ROWB + col2;
                    *(uint32_t*)(smem + SM_YH + o0) = pkh2(v0, v1);
                    *(uint32_t*)(smem + SM_YH + o1) = pkh2(v2, v3);
                }
            }
        }
        __syncthreads();

        // ===== L2: Y (cols branch*64..+63) -> X, 16-col slice per warp =====
        {
            const int colout = branch * 64 + nw2;
            const uint32_t abase = (uint32_t)branch * 128u;
#pragma unroll 1
            for (int mt = 0; mt < 8; mt++) {
                int m0 = mt * 16;
                float aP[2][4] = {}, aQ[2][4] = {};
                uint32_t arow = (uint32_t)(m0 + (lane & 15)) * ROWB + abase + (lane >> 4) * 16u;
#pragma unroll
                for (int kt = 0; kt < 4; kt++) {
                    uint32_t h0, h1, h2, h3;
                    ldsm4(yh + arow + kt * 32u, h0, h1, h2, h3);
#pragma unroll
                    for (int nt = 0; nt < 2; nt++) {
                        mma16816(aP[nt], h0, h1, h2, h3, B2h[kt][nt][0], B2h[kt][nt][1]);
                        mma16816(aQ[nt], h0, h1, h2, h3, B2l[kt][nt][0], B2l[kt][nt][1]);
                    }
                }
#pragma unroll
                for (int nt = 0; nt < 2; nt++) {
                    float v0 = lrelu(fmaf(aQ[nt][0], LO_INV, aP[nt][0]) + b2v[nt][0]);
                    float v1 = lrelu(fmaf(aQ[nt][1], LO_INV, aP[nt][1]) + b2v[nt][1]);
                    float v2 = lrelu(fmaf(aQ[nt][2], LO_INV, aP[nt][2]) + b2v[nt][0]);
                    float v3 = lrelu(fmaf(aQ[nt][3], LO_INV, aP[nt][3]) + b2v[nt][1]);
                    uint32_t col2 = (uint32_t)(colout + nt * 8 + (lane & 3) * 2) * 2u;
                    uint32_t o0 = (uint32_t)(m0 + (lane >> 2)) * ROWB + col2;
                    uint32_t o1 = (uint32_t)(m0 + 8 + (lane >> 2)) * ROWB + col2;
                    *(uint32_t*)(smem + SM_XH + o0) = pkh2(v0, v1);
                    *(uint32_t*)(smem + SM_XH + o1) = pkh2(v2, v3);
                }
            }
        }
        __syncthreads();

        // ===== L3 + L4: X (cols branch*64..) -> partials in P =====
        {
            const uint32_t abase = (uint32_t)branch * 128u;
            float* P = (float*)(smem + SM_P);
#pragma unroll 1
            for (int i = 0; i < 4; i++) {
                int m0 = (mg * 4 + i) * 16;
                float aP[2][4] = {}, aQ[2][4] = {};
                uint32_t arow = (uint32_t)(m0 + (lane & 15)) * ROWB + abase + (lane >> 4) * 16u;
#pragma unroll
                for (int kt = 0; kt < 4; kt++) {
                    uint32_t h0, h1, h2, h3;
                    ldsm4(xh + arow + kt * 32u, h0, h1, h2, h3);
#pragma unroll
                    for (int nt = 0; nt < 2; nt++) {
                        mma16816(aP[nt], h0, h1, h2, h3, B3h[kt][nt][0], B3h[kt][nt][1]);
                        mma16816(aQ[nt], h0, h1, h2, h3, B3l[kt][nt][0], B3l[kt][nt][1]);
                    }
                }
                float p0 = 0.0f, p1 = 0.0f;
#pragma unroll
                for (int nt = 0; nt < 2; nt++) {
                    p0 += lrelu(fmaf(aQ[nt][0], LO_INV, aP[nt][0]) + b3v[nt][0]) * w4v[nt][0] +
                          lrelu(fmaf(aQ[nt][1], LO_INV, aP[nt][1]) + b3v[nt][1]) * w4v[nt][1];
                    p1 += lrelu(fmaf(aQ[nt][2], LO_INV, aP[nt][2]) + b3v[nt][0]) * w4v[nt][0] +
                          lrelu(fmaf(aQ[nt][3], LO_INV, aP[nt][3]) + b3v[nt][1]) * w4v[nt][1];
                }
                p0 += __shfl_xor_sync(0xFFFFFFFFu, p0, 1);
                p0 += __shfl_xor_sync(0xFFFFFFFFu, p0, 2);
                p1 += __shfl_xor_sync(0xFFFFFFFFu, p1, 1);
                p1 += __shfl_xor_sync(0xFFFFFFFFu, p1, 2);
                if ((lane & 3) == 0) {
                    int r0 = m0 + (lane >> 2);
                    int ns = nw3 >> 4;     // 0 or 1
                    P[((branch << 7) + r0) * 2 + ns] = p0;
                    P[((branch << 7) + r0 + 8) * 2 + ns] = p1;
                }
            }
        }
        __syncthreads();

        // ===== final reduce + store =====
        {
            int br = tid >> 7, m = tid & 127;
            float2 pv = *(const float2*)(smem + SM_P + ((br << 7) + m) * 8);
            float b4 = *(const float*)(smem + SM_B4 + br * 4);
            out[br * NEDGES + t * TILE_M + m] = pv.x + pv.y + b4;
        }
        // hazards: gather (next X writer) runs after this point but the last X
        // readers (L3 ldmatrix) finished before the sync above; P is rewritten
        // only after 3 more syncs.
    }
}

extern "C" void kernel_launch(void* const* d_in, const int* in_sizes, int n_in,
                              void* d_out, int out_size) {
    const float* x_src = (const float*)d_in[0];
    const float* x_dst = (const float*)d_in[1];
    const int* eidx = (const int*)d_in[2];
    const float* ew1 = (const float*)d_in[3];
    const float* eb1 = (const float*)d_in[4];
    const float* ww1 = (const float*)d_in[5];
    const float* wb1 = (const float*)d_in[6];
    const float* ew2 = (const float*)d_in[7];
    const float* eb2 = (const float*)d_in[8];
    const float* ww2 = (const float*)d_in[9];
    const float* wb2 = (const float*)d_in[10];
    const float* ew3 = (const float*)d_in[11];
    const float* eb3 = (const float*)d_in[12];
    const float* ww3 = (const float*)d_in[13];
    const float* wb3 = (const float*)d_in[14];
    const float* ew4 = (const float*)d_in[15];
    const float* eb4 = (const float*)d_in[16];
    const float* ww4 = (const float*)d_in[17];
    const float* wb4 = (const float*)d_in[18];
    float* out = (float*)d_out;

    int nsm = 148;
    cudaDeviceGetAttribute(&nsm, cudaDevAttrMultiProcessorCount, 0);

    cudaFuncSetAttribute(regressor_mma_kernel,
                         cudaFuncAttributeMaxDynamicSharedMemorySize, SMEM_BYTES);

    regressor_mma_kernel<<<nsm, TPB, SMEM_BYTES>>>(
        x_src, x_dst, eidx, ew1, eb1, ww1, wb1, ew2, eb2, ww2, wb2,
        ew3, eb3, ww3, wb3, ew4, eb4, ww4, wb4, out);
}

// round 9
// speedup vs baseline: 1.0563x; 1.0563x over previous
#include <cuda_runtime.h>
#include <cuda_fp16.h>
#include <cstdint>

#define NEDGES 2000000
#define TILE_M 128
#define NTILES (NEDGES / TILE_M)
#define TPB 256

// X: [128 rows][136 fp16] stride 272 B (17*16: conflict-free ldmatrix)
// Y: [128 rows][72 fp16]  stride 144 B (9*16: conflict-free ldmatrix)
#define ROWB 272
#define ROWBY 144
#define SM_X  0                 // 34816 B
#define SM_Y  34816             // 18432 B
#define SM_P  53248             // float[128][4] = 2048 B
#define SM_B4 55296             // float[1]
#define SMEM_BYTES 55360

#define LO_SCALE 2048.0f        // 2^11: keep B-lo in fp16 normal range
#define LO_INV   (1.0f / 2048.0f)

__device__ __forceinline__ uint32_t smem_u32(const void* p) {
    uint32_t a;
    asm("{ .reg .u64 t; cvta.to.shared.u64 t, %1; cvt.u32.u64 %0, t; }" : "=r"(a) : "l"(p));
    return a;
}
__device__ __forceinline__ float lrelu(float z) { return fmaxf(z, 0.01f * z); }

// pack 2 f32 -> fp16x2 (a in low half)
__device__ __forceinline__ uint32_t pkh2(float a, float b) {
    __half2 h = __floats2half2_rn(a, b);
    return *(uint32_t*)&h;
}

__device__ __forceinline__ void ldsm4(uint32_t addr, uint32_t& a0, uint32_t& a1,
                                      uint32_t& a2, uint32_t& a3) {
    asm volatile("ldmatrix.sync.aligned.m8n8.x4.shared.b16 {%0,%1,%2,%3}, [%4];"
                 : "=r"(a0), "=r"(a1), "=r"(a2), "=r"(a3) : "r"(addr));
}
__device__ __forceinline__ void mma16816(float* d, uint32_t a0, uint32_t a1,
                                         uint32_t a2, uint32_t a3,
                                         uint32_t b0, uint32_t b1) {
    asm volatile(
        "mma.sync.aligned.m16n8k16.row.col.f32.f16.f16.f32 "
        "{%0,%1,%2,%3}, {%4,%5,%6,%7}, {%8,%9}, {%0,%1,%2,%3};"
        : "+f"(d[0]), "+f"(d[1]), "+f"(d[2]), "+f"(d[3])
        : "r"(a0), "r"(a1), "r"(a2), "r"(a3), "r"(b0), "r"(b1));
}

// 8x8 B fragment (col-major k8 x n8) from global W[k][n]: fp16 hi + scaled fp16 lo
__device__ __forceinline__ void make_hfrag(const float* __restrict__ W, int ldn,
                                           int k0, int n0, int lane,
                                           uint32_t& h, uint32_t& l) {
    int g = lane >> 2, tg = lane & 3;
    const float* p = W + (size_t)(k0 + tg * 2) * ldn + (n0 + g);
    float wa = p[0], wb = p[ldn];
    h = pkh2(wa, wb);
    __half2 hh = *(__half2*)&h;
    float ra = (wa - __low2float(hh)) * LO_SCALE;
    float rb = (wb - __high2float(hh)) * LO_SCALE;
    l = pkh2(ra, rb);
}

__global__ void __launch_bounds__(TPB, 2)
regressor_mma_kernel(const float* __restrict__ x_src,
                     const float* __restrict__ x_dst,
                     const int* __restrict__ eidx,
                     const float* __restrict__ ew1, const float* __restrict__ eb1,
                     const float* __restrict__ ww1, const float* __restrict__ wb1,
                     const float* __restrict__ ew2, const float* __restrict__ eb2,
                     const float* __restrict__ ww2, const float* __restrict__ wb2,
                     const float* __restrict__ ew3, const float* __restrict__ eb3,
                     const float* __restrict__ ww3, const float* __restrict__ wb3,
                     const float* __restrict__ ew4, const float* __restrict__ eb4,
                     const float* __restrict__ ww4, const float* __restrict__ wb4,
                     float* __restrict__ out) {
    extern __shared__ char smem[];
    const uint32_t smb = smem_u32(smem);
    const int tid = threadIdx.x;
    const int wid = tid >> 5, lane = tid & 31;

    const int branch = blockIdx.x & 1;     // CTA-level: 0 = exists, 1 = weight
    const int nw = wid * 8;                // 8-col n-slice of this branch (L1/L2)
    const int mg = wid >> 2;               // L3 m-group (0: mt 0-3, 1: mt 4-7)
    const int n3 = (wid & 3) * 8;          // L3 n-slice

    // ---------- per-warp weight fragments (registers, built once) ----------
    const float* W1 = branch ? ww1 : ew1;  // [128][64]
    const float* W2 = branch ? ww2 : ew2;  // [64][64]
    const float* W3 = branch ? ww3 : ew3;  // [64][32]
    const float* B1 = branch ? wb1 : eb1;
    const float* B2 = branch ? wb2 : eb2;
    const float* B3 = branch ? wb3 : eb3;
    const float* W4 = branch ? ww4 : ew4;

    uint32_t B1h[8][2], B1l[8][2];
#pragma unroll
    for (int kt = 0; kt < 8; kt++)
#pragma unroll
        for (int r = 0; r < 2; r++)
            make_hfrag(W1, 64, kt * 16 + r * 8, nw, lane, B1h[kt][r], B1l[kt][r]);

    uint32_t B2h[4][2], B2l[4][2];
#pragma unroll
    for (int kt = 0; kt < 4; kt++)
#pragma unroll
        for (int r = 0; r < 2; r++)
            make_hfrag(W2, 64, kt * 16 + r * 8, nw, lane, B2h[kt][r], B2l[kt][r]);

    uint32_t B3h[4][2], B3l[4][2];
#pragma unroll
    for (int kt = 0; kt < 4; kt++)
#pragma unroll
        for (int r = 0; r < 2; r++)
            make_hfrag(W3, 32, kt * 16 + r * 8, n3, lane, B3h[kt][r], B3l[kt][r]);

    // per-thread biases / final weights for covered columns
    float b1v[2], b2v[2], b3v[2], w4v[2];
#pragma unroll
    for (int j = 0; j < 2; j++) {
        int c = nw + (lane & 3) * 2 + j;
        b1v[j] = B1[c];
        b2v[j] = B2[c];
        int c3 = n3 + (lane & 3) * 2 + j;
        b3v[j] = B3[c3];
        w4v[j] = W4[c3];
    }
    if (tid == 0)
        *(float*)(smem + SM_B4) = branch ? wb4[0] : eb4[0];
    __syncthreads();

    const uint32_t xb = smb + SM_X;
    const uint32_t yb = smb + SM_Y;
    const int tstep = gridDim.x >> 1;

    for (int t = blockIdx.x >> 1; t < NTILES; t += tstep) {
        // ===== gather: warp w owns edges [16w,16w+16); lanes 0-15 src, 16-31 dst =====
        {
            const int half = lane >> 4;
            const int c16 = lane & 15;
#pragma unroll 4
            for (int i = 0; i < 16; i++) {
                int m = wid * 16 + i;
                int e = t * TILE_M + m;
                int idx = half ? eidx[NEDGES + e] : eidx[e];
                const float* row = (half ? x_dst : x_src) + (size_t)idx * 64;
                float4 v = ((const float4*)row)[c16];
                uint32_t h0 = pkh2(v.x, v.y);
                uint32_t h1 = pkh2(v.z, v.w);
                uint32_t off = (uint32_t)m * ROWB + half * 128u + c16 * 8u;
                *(uint2*)(smem + SM_X + off) = make_uint2(h0, h1);
            }
        }
        __syncthreads();

        // ===== L1: X[128x128] -> Y[128x64], 8-col slice per warp =====
        {
#pragma unroll 1
            for (int mt = 0; mt < 8; mt++) {
                int m0 = mt * 16;
                float aP[4] = {}, aQ[4] = {};
                uint32_t arow = (uint32_t)(m0 + (lane & 15)) * ROWB + (lane >> 4) * 16u;
#pragma unroll
                for (int kt = 0; kt < 8; kt++) {
                    uint32_t h0, h1, h2, h3;
                    ldsm4(xb + arow + kt * 32u, h0, h1, h2, h3);
                    mma16816(aP, h0, h1, h2, h3, B1h[kt][0], B1h[kt][1]);
                    mma16816(aQ, h0, h1, h2, h3, B1l[kt][0], B1l[kt][1]);
                }
                float v0 = lrelu(fmaf(aQ[0], LO_INV, aP[0]) + b1v[0]);
                float v1 = lrelu(fmaf(aQ[1], LO_INV, aP[1]) + b1v[1]);
                float v2 = lrelu(fmaf(aQ[2], LO_INV, aP[2]) + b1v[0]);
                float v3 = lrelu(fmaf(aQ[3], LO_INV, aP[3]) + b1v[1]);
                uint32_t col2 = (uint32_t)(nw + (lane & 3) * 2) * 2u;
                uint32_t o0 = (uint32_t)(m0 + (lane >> 2)) * ROWBY + col2;
                uint32_t o1 = (uint32_t)(m0 + 8 + (lane >> 2)) * ROWBY + col2;
                *(uint32_t*)(smem + SM_Y + o0) = pkh2(v0, v1);
                *(uint32_t*)(smem + SM_Y + o1) = pkh2(v2, v3);
            }
        }
        __syncthreads();

        // ===== L2: Y[128x64] -> X cols 0..63, 8-col slice per warp =====
        {
#pragma unroll 1
            for (int mt = 0; mt < 8; mt++) {
                int m0 = mt * 16;
                float aP[4] = {}, aQ[4] = {};
                uint32_t arow = (uint32_t)(m0 + (lane & 15)) * ROWBY + (lane >> 4) * 16u;
#pragma unroll
                for (int kt = 0; kt < 4; kt++) {
                    uint32_t h0, h1, h2, h3;
                    ldsm4(yb + arow + kt * 32u, h0, h1, h2, h3);
                    mma16816(aP, h0, h1, h2, h3, B2h[kt][0], B2h[kt][1]);
                    mma16816(aQ, h0, h1, h2, h3, B2l[kt][0], B2l[kt][1]);
                }
                float v0 = lrelu(fmaf(aQ[0], LO_INV, aP[0]) + b2v[0]);
                float v1 = lrelu(fmaf(aQ[1], LO_INV, aP[1]) + b2v[1]);
                float v2 = lrelu(fmaf(aQ[2], LO_INV, aP[2]) + b2v[0]);
                float v3 = lrelu(fmaf(aQ[3], LO_INV, aP[3]) + b2v[1]);
                uint32_t col2 = (uint32_t)(nw + (lane & 3) * 2) * 2u;
                uint32_t o0 = (uint32_t)(m0 + (lane >> 2)) * ROWB + col2;
                uint32_t o1 = (uint32_t)(m0 + 8 + (lane >> 2)) * ROWB + col2;
                *(uint32_t*)(smem + SM_X + o0) = pkh2(v0, v1);
                *(uint32_t*)(smem + SM_X + o1) = pkh2(v2, v3);
            }
        }
        __syncthreads();

        // ===== L3 + L4: X cols 0..63 -> partials in P =====
        {
            float* P = (float*)(smem + SM_P);
#pragma unroll 1
            for (int i = 0; i < 4; i++) {
                int m0 = (mg * 4 + i) * 16;
                float aP[4] = {}, aQ[4] = {};
                uint32_t arow = (uint32_t)(m0 + (lane & 15)) * ROWB + (lane >> 4) * 16u;
#pragma unroll
                for (int kt = 0; kt < 4; kt++) {
                    uint32_t h0, h1, h2, h3;
                    ldsm4(xb + arow + kt * 32u, h0, h1, h2, h3);
                    mma16816(aP, h0, h1, h2, h3, B3h[kt][0], B3h[kt][1]);
                    mma16816(aQ, h0, h1, h2, h3, B3l[kt][0], B3l[kt][1]);
                }
                float p0 = lrelu(fmaf(aQ[0], LO_INV, aP[0]) + b3v[0]) * w4v[0] +
                           lrelu(fmaf(aQ[1], LO_INV, aP[1]) + b3v[1]) * w4v[1];
                float p1 = lrelu(fmaf(aQ[2], LO_INV, aP[2]) + b3v[0]) * w4v[0] +
                           lrelu(fmaf(aQ[3], LO_INV, aP[3]) + b3v[1]) * w4v[1];
                p0 += __shfl_xor_sync(0xFFFFFFFFu, p0, 1);
                p0 += __shfl_xor_sync(0xFFFFFFFFu, p0, 2);
                p1 += __shfl_xor_sync(0xFFFFFFFFu, p1, 1);
                p1 += __shfl_xor_sync(0xFFFFFFFFu, p1, 2);
                if ((lane & 3) == 0) {
                    int r0 = m0 + (lane >> 2);
                    P[r0 * 4 + (wid & 3)] = p0;
                    P[(r0 + 8) * 4 + (wid & 3)] = p1;
                }
            }
        }
        __syncthreads();

        // ===== final reduce + store (128 threads) =====
        if (tid < 128) {
            float4 pv = *(const float4*)(smem + SM_P + tid * 16);
            float b4 = *(const float*)(smem + SM_B4);
            out[branch * NEDGES + t * TILE_M + tid] = pv.x + pv.y + pv.z + pv.w + b4;
        }
        // hazards: next gather writes X — last X readers (L3) done before the
        // sync above; store reads P (disjoint from X), P rewritten only after
        // 3 more syncs.
    }
}

extern "C" void kernel_launch(void* const* d_in, const int* in_sizes, int n_in,
                              void* d_out, int out_size) {
    const float* x_src = (const float*)d_in[0];
    const float* x_dst = (const float*)d_in[1];
    const int* eidx = (const int*)d_in[2];
    const float* ew1 = (const float*)d_in[3];
    const float* eb1 = (const float*)d_in[4];
    const float* ww1 = (const float*)d_in[5];
    const float* wb1 = (const float*)d_in[6];
    const float* ew2 = (const float*)d_in[7];
    const float* eb2 = (const float*)d_in[8];
    const float* ww2 = (const float*)d_in[9];
    const float* wb2 = (const float*)d_in[10];
    const float* ew3 = (const float*)d_in[11];
    const float* eb3 = (const float*)d_in[12];
    const float* ww3 = (const float*)d_in[13];
    const float* wb3 = (const float*)d_in[14];
    const float* ew4 = (const float*)d_in[15];
    const float* eb4 = (const float*)d_in[16];
    const float* ww4 = (const float*)d_in[17];
    const float* wb4 = (const float*)d_in[18];
    float* out = (float*)d_out;

    int nsm = 148;
    cudaDeviceGetAttribute(&nsm, cudaDevAttrMultiProcessorCount, 0);

    cudaFuncSetAttribute(regressor_mma_kernel,
                         cudaFuncAttributeMaxDynamicSharedMemorySize, SMEM_BYTES);

    regressor_mma_kernel<<<2 * nsm, TPB, SMEM_BYTES>>>(
        x_src, x_dst, eidx, ew1, eb1, ww1, wb1, ew2, eb2, ww2, wb2,
        ew3, eb3, ww3, wb3, ew4, eb4, ww4, wb4, out);
}

// round 10
// speedup vs baseline: 1.7494x; 1.6563x over previous
#include <cuda_runtime.h>
#include <cuda_fp16.h>
#include <cstdint>

#define NEDGES 2000000
#define TILE_M 128
#define NTILES (NEDGES / TILE_M)
#define TPB 512

// X, Y: [128 rows][136 fp16] stride 272 B (17*16: conflict-free ldmatrix)
#define ROWB 272
#define SM_X  0                 // 34816 B
#define SM_Y  34816             // 34816 B
#define SM_P  69632             // float[2][128][2] = 2048 B
#define SM_B4 71680             // float[2]
#define SMEM_BYTES 71744

__device__ __forceinline__ uint32_t smem_u32(const void* p) {
    uint32_t a;
    asm("{ .reg .u64 t; cvta.to.shared.u64 t, %1; cvt.u32.u64 %0, t; }" : "=r"(a) : "l"(p));
    return a;
}
__device__ __forceinline__ float lrelu(float z) { return fmaxf(z, 0.01f * z); }

// pack 2 f32 -> fp16x2 (a in low half)
__device__ __forceinline__ uint32_t pkh2(float a, float b) {
    __half2 h = __floats2half2_rn(a, b);
    return *(uint32_t*)&h;
}

__device__ __forceinline__ void ldsm4(uint32_t addr, uint32_t& a0, uint32_t& a1,
                                      uint32_t& a2, uint32_t& a3) {
    asm volatile("ldmatrix.sync.aligned.m8n8.x4.shared.b16 {%0,%1,%2,%3}, [%4];"
                 : "=r"(a0), "=r"(a1), "=r"(a2), "=r"(a3) : "r"(addr));
}
__device__ __forceinline__ void mma16816(float* d, uint32_t a0, uint32_t a1,
                                         uint32_t a2, uint32_t a3,
                                         uint32_t b0, uint32_t b1) {
    asm volatile(
        "mma.sync.aligned.m16n8k16.row.col.f32.f16.f16.f32 "
        "{%0,%1,%2,%3}, {%4,%5,%6,%7}, {%8,%9}, {%0,%1,%2,%3};"
        : "+f"(d[0]), "+f"(d[1]), "+f"(d[2]), "+f"(d[3])
        : "r"(a0), "r"(a1), "r"(a2), "r"(a3), "r"(b0), "r"(b1));
}

// 8x8 B fragment (col-major k8 x n8) from global W[k][n], fp16 (hi only)
__device__ __forceinline__ uint32_t make_hfrag(const float* __restrict__ W, int ldn,
                                               int k0, int n0, int lane) {
    int g = lane >> 2, tg = lane & 3;
    const float* p = W + (size_t)(k0 + tg * 2) * ldn + (n0 + g);
    return pkh2(p[0], p[ldn]);
}

__global__ void __launch_bounds__(TPB, 1)
regressor_mma_kernel(const float* __restrict__ x_src,
                     const float* __restrict__ x_dst,
                     const int* __restrict__ eidx,
                     const float* __restrict__ ew1, const float* __restrict__ eb1,
                     const float* __restrict__ ww1, const float* __restrict__ wb1,
                     const float* __restrict__ ew2, const float* __restrict__ eb2,
                     const float* __restrict__ ww2, const float* __restrict__ wb2,
                     const float* __restrict__ ew3, const float* __restrict__ eb3,
                     const float* __restrict__ ww3, const float* __restrict__ wb3,
                     const float* __restrict__ ew4, const float* __restrict__ eb4,
                     const float* __restrict__ ww4, const float* __restrict__ wb4,
                     float* __restrict__ out) {
    extern __shared__ char smem[];
    const uint32_t smb = smem_u32(smem);
    const int tid = threadIdx.x;
    const int wid = tid >> 5, lane = tid & 31;

    const int branch = wid >> 3;           // 0 = exists, 1 = weight
    const int w8 = wid & 7;
    const int mh = w8 >> 2;                // L1/L2 m-half (4 mt each)
    const int nL = (w8 & 3) * 16;          // L1/L2 16-col n-slice of branch
    const int mg = w8 >> 1;                // L3 m-group (2 mt each)
    const int ns3 = w8 & 1;                // L3 n-slice index
    const int n3 = ns3 * 16;               // L3 16-col n-slice

    // ---------- per-warp weight fragments (fp16 hi, registers) ----------
    const float* W1 = branch ? ww1 : ew1;  // [128][64]
    const float* W2 = branch ? ww2 : ew2;  // [64][64]
    const float* W3 = branch ? ww3 : ew3;  // [64][32]
    const float* B1 = branch ? wb1 : eb1;
    const float* B2 = branch ? wb2 : eb2;
    const float* B3 = branch ? wb3 : eb3;
    const float* W4 = branch ? ww4 : ew4;

    uint32_t B1h[8][2][2];
#pragma unroll
    for (int kt = 0; kt < 8; kt++)
#pragma unroll
        for (int nt = 0; nt < 2; nt++)
#pragma unroll
            for (int r = 0; r < 2; r++)
                B1h[kt][nt][r] = make_hfrag(W1, 64, kt * 16 + r * 8, nL + nt * 8, lane);

    uint32_t B2h[4][2][2];
#pragma unroll
    for (int kt = 0; kt < 4; kt++)
#pragma unroll
        for (int nt = 0; nt < 2; nt++)
#pragma unroll
            for (int r = 0; r < 2; r++)
                B2h[kt][nt][r] = make_hfrag(W2, 64, kt * 16 + r * 8, nL + nt * 8, lane);

    uint32_t B3h[4][2][2];
#pragma unroll
    for (int kt = 0; kt < 4; kt++)
#pragma unroll
        for (int nt = 0; nt < 2; nt++)
#pragma unroll
            for (int r = 0; r < 2; r++)
                B3h[kt][nt][r] = make_hfrag(W3, 32, kt * 16 + r * 8, n3 + nt * 8, lane);

    // per-thread biases / final weights for covered columns
    float b1v[2][2], b2v[2][2], b3v[2][2], w4v[2][2];
#pragma unroll
    for (int nt = 0; nt < 2; nt++)
#pragma unroll
        for (int j = 0; j < 2; j++) {
            int c = nL + nt * 8 + (lane & 3) * 2 + j;
            b1v[nt][j] = B1[c];
            b2v[nt][j] = B2[c];
            int c3 = n3 + nt * 8 + (lane & 3) * 2 + j;
            b3v[nt][j] = B3[c3];
            w4v[nt][j] = W4[c3];
        }
    if (tid == 0) {
        *(float*)(smem + SM_B4 + 0) = eb4[0];
        *(float*)(smem + SM_B4 + 4) = wb4[0];
    }
    __syncthreads();

    const uint32_t xb = smb + SM_X;
    const uint32_t yb = smb + SM_Y;

    for (int t = blockIdx.x; t < NTILES; t += gridDim.x) {
        // ===== gather: warp w owns edges [8w, 8w+8); lanes 0-15 src, 16-31 dst =====
        {
            const int half = lane >> 4;
            const int c16 = lane & 15;
#pragma unroll 4
            for (int i = 0; i < 8; i++) {
                int m = wid * 8 + i;
                int e = t * TILE_M + m;
                int idx = half ? eidx[NEDGES + e] : eidx[e];
                const float* row = (half ? x_dst : x_src) + (size_t)idx * 64;
                float4 v = ((const float4*)row)[c16];
                uint32_t h0 = pkh2(v.x, v.y);
                uint32_t h1 = pkh2(v.z, v.w);
                uint32_t off = (uint32_t)m * ROWB + half * 128u + c16 * 8u;
                *(uint2*)(smem + SM_X + off) = make_uint2(h0, h1);
            }
        }
        __syncthreads();

        // ===== L1: X[128x128] -> Y[128x128]; warp: m-half mh, 16-col slice =====
        {
            const int colout = branch * 64 + nL;
#pragma unroll 1
            for (int i = 0; i < 4; i++) {
                int m0 = (mh * 4 + i) * 16;
                float aP[2][4] = {};
                uint32_t arow = (uint32_t)(m0 + (lane & 15)) * ROWB + (lane >> 4) * 16u;
#pragma unroll
                for (int kt = 0; kt < 8; kt++) {
                    uint32_t h0, h1, h2, h3;
                    ldsm4(xb + arow + kt * 32u, h0, h1, h2, h3);
                    mma16816(aP[0], h0, h1, h2, h3, B1h[kt][0][0], B1h[kt][0][1]);
                    mma16816(aP[1], h0, h1, h2, h3, B1h[kt][1][0], B1h[kt][1][1]);
                }
#pragma unroll
                for (int nt = 0; nt < 2; nt++) {
                    float v0 = lrelu(aP[nt][0] + b1v[nt][0]);
                    float v1 = lrelu(aP[nt][1] + b1v[nt][1]);
                    float v2 = lrelu(aP[nt][2] + b1v[nt][0]);
                    float v3 = lrelu(aP[nt][3] + b1v[nt][1]);
                    uint32_t col2 = (uint32_t)(colout + nt * 8 + (lane & 3) * 2) * 2u;
                    uint32_t o0 = (uint32_t)(m0 + (lane >> 2)) * ROWB + col2;
                    uint32_t o1 = (uint32_t)(m0 + 8 + (lane >> 2)) * ROWB + col2;
                    *(uint32_t*)(smem + SM_Y + o0) = pkh2(v0, v1);
                    *(uint32_t*)(smem + SM_Y + o1) = pkh2(v2, v3);
                }
            }
        }
        __syncthreads();

        // ===== L2: Y (cols branch*64..) -> X (cols branch*64..) =====
        {
            const int colout = branch * 64 + nL;
            const uint32_t abase = (uint32_t)branch * 128u;
#pragma unroll 1
            for (int i = 0; i < 4; i++) {
                int m0 = (mh * 4 + i) * 16;
                float aP[2][4] = {};
                uint32_t arow = (uint32_t)(m0 + (lane & 15)) * ROWB + abase + (lane >> 4) * 16u;
#pragma unroll
                for (int kt = 0; kt < 4; kt++) {
                    uint32_t h0, h1, h2, h3;
                    ldsm4(yb + arow + kt * 32u, h0, h1, h2, h3);
                    mma16816(aP[0], h0, h1, h2, h3, B2h[kt][0][0], B2h[kt][0][1]);
                    mma16816(aP[1], h0, h1, h2, h3, B2h[kt][1][0], B2h[kt][1][1]);
                }
#pragma unroll
                for (int nt = 0; nt < 2; nt++) {
                    float v0 = lrelu(aP[nt][0] + b2v[nt][0]);
                    float v1 = lrelu(aP[nt][1] + b2v[nt][1]);
                    float v2 = lrelu(aP[nt][2] + b2v[nt][0]);
                    float v3 = lrelu(aP[nt][3] + b2v[nt][1]);
                    uint32_t col2 = (uint32_t)(colout + nt * 8 + (lane & 3) * 2) * 2u;
                    uint32_t o0 = (uint32_t)(m0 + (lane >> 2)) * ROWB + col2;
                    uint32_t o1 = (uint32_t)(m0 + 8 + (lane >> 2)) * ROWB + col2;
                    *(uint32_t*)(smem + SM_X + o0) = pkh2(v0, v1);
                    *(uint32_t*)(smem + SM_X + o1) = pkh2(v2, v3);
                }
            }
        }
        __syncthreads();

        // ===== L3 + L4: X (cols branch*64..) -> partials in P =====
        {
            const uint32_t abase = (uint32_t)branch * 128u;
            float* P = (float*)(smem + SM_P);
#pragma unroll 1
            for (int i = 0; i < 2; i++) {
                int m0 = (mg * 2 + i) * 16;
                float aP[2][4] = {};
                uint32_t arow = (uint32_t)(m0 + (lane & 15)) * ROWB + abase + (lane >> 4) * 16u;
#pragma unroll
                for (int kt = 0; kt < 4; kt++) {
                    uint32_t h0, h1, h2, h3;
                    ldsm4(xb + arow + kt * 32u, h0, h1, h2, h3);
                    mma16816(aP[0], h0, h1, h2, h3, B3h[kt][0][0], B3h[kt][0][1]);
                    mma16816(aP[1], h0, h1, h2, h3, B3h[kt][1][0], B3h[kt][1][1]);
                }
                float p0 = 0.0f, p1 = 0.0f;
#pragma unroll
                for (int nt = 0; nt < 2; nt++) {
                    p0 += lrelu(aP[nt][0] + b3v[nt][0]) * w4v[nt][0] +
                          lrelu(aP[nt][1] + b3v[nt][1]) * w4v[nt][1];
                    p1 += lrelu(aP[nt][2] + b3v[nt][0]) * w4v[nt][0] +
                          lrelu(aP[nt][3] + b3v[nt][1]) * w4v[nt][1];
                }
                p0 += __shfl_xor_sync(0xFFFFFFFFu, p0, 1);
                p0 += __shfl_xor_sync(0xFFFFFFFFu, p0, 2);
                p1 += __shfl_xor_sync(0xFFFFFFFFu, p1, 1);
                p1 += __shfl_xor_sync(0xFFFFFFFFu, p1, 2);
                if ((lane & 3) == 0) {
                    int r0 = m0 + (lane >> 2);
                    P[((branch << 7) + r0) * 2 + ns3] = p0;
                    P[((branch << 7) + r0 + 8) * 2 + ns3] = p1;
                }
            }
        }
        __syncthreads();

        // ===== final reduce + store (256 threads) =====
        if (tid < 256) {
            int br = tid >> 7, m = tid & 127;
            float2 pv = *(const float2*)(smem + SM_P + ((br << 7) + m) * 8);
            float b4 = *(const float*)(smem + SM_B4 + br * 4);
            out[br * NEDGES + t * TILE_M + m] = pv.x + pv.y + b4;
        }
        // hazards: next gather writes X — last X readers (L3 ldmatrix) done
        // before the sync above; P is rewritten only after 3 more syncs.
    }
}

extern "C" void kernel_launch(void* const* d_in, const int* in_sizes, int n_in,
                              void* d_out, int out_size) {
    const float* x_src = (const float*)d_in[0];
    const float* x_dst = (const float*)d_in[1];
    const int* eidx = (const int*)d_in[2];
    const float* ew1 = (const float*)d_in[3];
    const float* eb1 = (const float*)d_in[4];
    const float* ww1 = (const float*)d_in[5];
    const float* wb1 = (const float*)d_in[6];
    const float* ew2 = (const float*)d_in[7];
    const float* eb2 = (const float*)d_in[8];
    const float* ww2 = (const float*)d_in[9];
    const float* wb2 = (const float*)d_in[10];
    const float* ew3 = (const float*)d_in[11];
    const float* eb3 = (const float*)d_in[12];
    const float* ww3 = (const float*)d_in[13];
    const float* wb3 = (const float*)d_in[14];
    const float* ew4 = (const float*)d_in[15];
    const float* eb4 = (const float*)d_in[16];
    const float* ww4 = (const float*)d_in[17];
    const float* wb4 = (const float*)d_in[18];
    float* out = (float*)d_out;

    int nsm = 148;
    cudaDeviceGetAttribute(&nsm, cudaDevAttrMultiProcessorCount, 0);

    cudaFuncSetAttribute(regressor_mma_kernel,
                         cudaFuncAttributeMaxDynamicSharedMemorySize, SMEM_BYTES);

    regressor_mma_kernel<<<nsm, TPB, SMEM_BYTES>>>(
        x_src, x_dst, eidx, ew1, eb1, ww1, wb1, ew2, eb2, ww2, wb2,
        ew3, eb3, ww3, wb3, ew4, eb4, ww4, wb4, out);
}